// round 17
// baseline (speedup 1.0000x reference)
#include <cuda_runtime.h>

#define NT   10
#define DIMX 240
#define NSC  64
#define NF   112
#define EPSV 1e-5f
#define NBLK 592
#define MAXB 204800

// scratch layout: [sum2: NT*DIMX][sum1: NT*NSC]
#define SCR_SUM1 (NT*DIMX)
#define SCR_SIZE (NT*DIMX + NT*NSC)

__device__ float    g_scr[SCR_SIZE];          // zeroed by apply block 0 each replay
__device__ int      g_tot[NT];                // per-type totals (reset by apply)
__device__ int      g_bh[NBLK*NT];            // per-block histograms (overwritten)
__device__ __align__(16) int g_perm[MAXB];    // row indices grouped by type
__device__ unsigned g_done;                   // stats arrival counter
__device__ __align__(16) float g_A[NT*DIMX];
__device__ __align__(16) float g_B[NT*DIMX];

// f32x2 register accumulate: a += v*v  /  a += v
__device__ __forceinline__ void fma2(unsigned long long& a, unsigned long long v) {
    asm("fma.rn.f32x2 %0, %1, %1, %0;" : "+l"(a) : "l"(v));
}
__device__ __forceinline__ void add2(unsigned long long& a, unsigned long long v) {
    asm("add.rn.f32x2 %0, %0, %1;" : "+l"(a) : "l"(v));
}
__device__ __forceinline__ float2 up2(unsigned long long v) {
    float2 f; asm("mov.b64 {%0, %1}, %2;" : "=f"(f.x), "=f"(f.y) : "l"(v)); return f;
}

// ---------------------------------------------------------------- histogram
__global__ __launch_bounds__(256) void k_hist(const int* __restrict__ ty,
                                              int batch, int chunk) {
    __shared__ int h[NT];
    const int tid = threadIdx.x;
    if (tid < NT) h[tid] = 0;
    __syncthreads();
    const int lo = blockIdx.x * chunk, hi = min(batch, lo + chunk);
    for (int r = lo + tid; r < hi; r += 256) atomicAdd(&h[ty[r]], 1);
    __syncthreads();
    if (tid < NT) {
        g_bh[blockIdx.x * NT + tid] = h[tid];
        atomicAdd(&g_tot[tid], h[tid]);
    }
}

// ---------------------------------------------------------------- scatter
// Block b computes its own base offsets (typeStart + sum of prior blocks'
// histograms) and scatters its rows' indices into g_perm grouped by type.
__global__ __launch_bounds__(256) void k_scatter(const int* __restrict__ ty,
                                                 int batch, int chunk) {
    __shared__ int cur[NT];
    const int tid = threadIdx.x;
    if (tid < NT) cur[tid] = 0;
    __syncthreads();

    int p[NT];
#pragma unroll
    for (int t = 0; t < NT; t++) p[t] = 0;
    for (int b2 = tid; b2 < (int)blockIdx.x; b2 += 256) {
#pragma unroll
        for (int t = 0; t < NT; t++) p[t] += g_bh[b2 * NT + t];
    }
#pragma unroll
    for (int t = 0; t < NT; t++) if (p[t]) atomicAdd(&cur[t], p[t]);
    __syncthreads();
    if (tid == 0) {
        int run = 0;
#pragma unroll
        for (int t = 0; t < NT; t++) { int tt = g_tot[t]; cur[t] += run; run += tt; }
    }
    __syncthreads();

    const int lo = blockIdx.x * chunk, hi = min(batch, lo + chunk);
    for (int r = lo + tid; r < hi; r += 256) {
        int t   = ty[r];
        int pos = atomicAdd(&cur[t], 1);
        g_perm[pos] = r;
    }
}

// ---------------------------------------------------------------- stats pass
// Block owns sorted positions [lo,hi). For each type segment intersecting its
// range: pure register accumulation (no smem histogram), flush via atomics.
//   rs = tid/60 : row subgroup (4 contiguous rows per thread per 16-row iter)
//   c4 = tid%60 : float4 column group
// Last block builds the A/B tables (counts come from g_tot).
__global__ __launch_bounds__(256) void k_stats(const float* __restrict__ x,
                                               const float* __restrict__ w,
                                               const float* __restrict__ bia,
                                               int batch, int chunk) {
    __shared__ unsigned sIsLast;
    const int tid = threadIdx.x;

    int pref[NT + 1];
    {
        int run = 0;
#pragma unroll
        for (int t = 0; t < NT; t++) { pref[t] = run; run += g_tot[t]; }
        pref[NT] = run;
    }

    const int  rs  = tid / 60;
    const int  c4  = tid - rs * 60;
    const int  c   = c4 * 4;
    const bool act = (tid < 240);
    const bool sc  = act && (c4 < 16);
    const int  lo  = blockIdx.x * chunk, hi = min(batch, lo + chunk);

    if (act && lo < hi) {
#pragma unroll
        for (int t = 0; t < NT; t++) {
            int sLo = pref[t]     > lo ? pref[t]     : lo;
            int sHi = pref[t + 1] < hi ? pref[t + 1] : hi;
            if (sLo >= sHi) continue;

            unsigned long long a0 = 0, a1 = 0, q0 = 0, q1 = 0;
            int r = sLo;
            // head-peel to 4-alignment (rs group 0 only)
            while (r < sHi && (r & 3)) {
                if (rs == 0) {
                    int row = g_perm[r];
                    ulonglong2 v = *(const ulonglong2*)(x + (size_t)row * DIMX + c);
                    fma2(a0, v.x); fma2(a1, v.y);
                    if (sc) { add2(q0, v.x); add2(q1, v.y); }
                }
                r++;
            }
            // main loop: 16 rows per iteration, 4 contiguous per thread
            for (; r + 16 <= sHi; r += 16) {
                int4 p = *(const int4*)(g_perm + r + rs * 4);
                ulonglong2 v0 = *(const ulonglong2*)(x + (size_t)p.x * DIMX + c);
                ulonglong2 v1 = *(const ulonglong2*)(x + (size_t)p.y * DIMX + c);
                ulonglong2 v2 = *(const ulonglong2*)(x + (size_t)p.z * DIMX + c);
                ulonglong2 v3 = *(const ulonglong2*)(x + (size_t)p.w * DIMX + c);
                fma2(a0, v0.x); fma2(a1, v0.y);
                fma2(a0, v1.x); fma2(a1, v1.y);
                fma2(a0, v2.x); fma2(a1, v2.y);
                fma2(a0, v3.x); fma2(a1, v3.y);
                if (sc) {
                    add2(q0, v0.x); add2(q1, v0.y);
                    add2(q0, v1.x); add2(q1, v1.y);
                    add2(q0, v2.x); add2(q1, v2.y);
                    add2(q0, v3.x); add2(q1, v3.y);
                }
            }
            // tail rows (<16): this thread's slots r+4rs+i
#pragma unroll
            for (int i = 0; i < 4; i++) {
                int rr = r + rs * 4 + i;
                if (rr < sHi) {
                    int row = g_perm[rr];
                    ulonglong2 v = *(const ulonglong2*)(x + (size_t)row * DIMX + c);
                    fma2(a0, v.x); fma2(a1, v.y);
                    if (sc) { add2(q0, v.x); add2(q1, v.y); }
                }
            }
            // flush segment partials
            float2 f0 = up2(a0), f1 = up2(a1);
            atomicAdd(&g_scr[t * DIMX + c + 0], f0.x);
            atomicAdd(&g_scr[t * DIMX + c + 1], f0.y);
            atomicAdd(&g_scr[t * DIMX + c + 2], f1.x);
            atomicAdd(&g_scr[t * DIMX + c + 3], f1.y);
            if (sc) {
                float2 h0 = up2(q0), h1 = up2(q1);
                atomicAdd(&g_scr[SCR_SUM1 + t * NSC + c + 0], h0.x);
                atomicAdd(&g_scr[SCR_SUM1 + t * NSC + c + 1], h0.y);
                atomicAdd(&g_scr[SCR_SUM1 + t * NSC + c + 2], h1.x);
                atomicAdd(&g_scr[SCR_SUM1 + t * NSC + c + 3], h1.y);
            }
        }
    }

    // ---- fused table build: last block to arrive does it ----
    __threadfence();
    __syncthreads();
    if (tid == 0)
        sIsLast = (atomicAdd(&g_done, 1u) == gridDim.x - 1u);
    __syncthreads();
    if (!sIsLast) return;
    __threadfence();

    const int e = tid;
    if (e < DIMX) {
        for (int tt = 0; tt < NT; tt++) {
            float cnt = fmaxf((float)(pref[tt + 1] - pref[tt]), 1.0f);
            float inv = 1.0f / cnt;
            float A, Bv;
            if (e < NSC) {
                float S2   = g_scr[tt * DIMX + e];
                float S1   = g_scr[SCR_SUM1 + tt * NSC + e];
                float mean = S1 * inv;
                float var  = S2 * inv - mean * mean;
                float s    = rsqrtf(var + EPSV) * w[tt * NF + e];
                A  = s;
                Bv = bia[tt * NSC + e] - mean * s;
            } else if (e < 64 + 32 * 3) {
                int m    = (e - 64) / 3;
                int bs   = 64 + m * 3;
                float S2 = g_scr[tt * DIMX + bs] + g_scr[tt * DIMX + bs + 1] +
                           g_scr[tt * DIMX + bs + 2];
                float fn = S2 * inv * (1.0f / 3.0f);
                A  = rsqrtf(fn + EPSV) * w[tt * NF + 64 + m];
                Bv = 0.0f;
            } else {
                int m    = (e - 160) / 5;
                int bs   = 160 + m * 5;
                float S2 = 0.0f;
#pragma unroll
                for (int j = 0; j < 5; j++) S2 += g_scr[tt * DIMX + bs + j];
                float fn = S2 * inv * 0.2f;
                A  = rsqrtf(fn + EPSV) * w[tt * NF + 96 + m];
                Bv = 0.0f;
            }
            g_A[tt * DIMX + e] = A;
            g_B[tt * DIMX + e] = Bv;
        }
    }
    if (tid == 0) g_done = 0;             // reset for next graph replay
}

// ---------------------------------------------------------------- apply pass
// Round-16 proven shape: reversed block order, 1024-float4 tile per block,
// 4 float4 per thread, JIT table gathers, streaming stores, 5 CTAs/SM.
// Block 0 resets g_scr and g_tot for the next graph replay.
__global__ __launch_bounds__(256, 5) void k_apply(const float4* __restrict__ x4,
                                                  const int* __restrict__ ty,
                                                  float4* __restrict__ o4,
                                                  int n4) {
    if (blockIdx.x == 0) {
        for (int i = threadIdx.x; i < SCR_SIZE; i += 256) g_scr[i] = 0.0f;
        if (threadIdx.x < NT) g_tot[threadIdx.x] = 0;
    }

    const unsigned chunk = gridDim.x - 1u - blockIdx.x;
    const unsigned ibase = chunk * 1024u + threadIdx.x;

    const float4* A4 = reinterpret_cast<const float4*>(g_A);
    const float4* B4 = reinterpret_cast<const float4*>(g_B);

    unsigned idx[4], k[4];
    bool     g[4];
    float4   xv[4];

#pragma unroll
    for (int j = 0; j < 4; j++) {
        idx[j] = ibase + j * 256u;
        g[j]   = idx[j] < (unsigned)n4;
    }
#pragma unroll
    for (int j = 0; j < 4; j++) {
        if (g[j]) {
            unsigned row = idx[j] / 60u;
            unsigned q   = idx[j] - row * 60u;
            int t = __ldg(ty + row);
            k[j]  = t * 60u + q;
            xv[j] = x4[idx[j]];
        }
    }
#pragma unroll
    for (int j = 0; j < 4; j++) {
        if (g[j]) {
            float4 a  = A4[k[j]];
            float4 bb = B4[k[j]];
            float4 o;
            o.x = fmaf(xv[j].x, a.x, bb.x);
            o.y = fmaf(xv[j].y, a.y, bb.y);
            o.z = fmaf(xv[j].z, a.z, bb.z);
            o.w = fmaf(xv[j].w, a.w, bb.w);
            __stcs(&o4[idx[j]], o);
        }
    }
}

// ---------------------------------------------------------------- launch
extern "C" void kernel_launch(void* const* d_in, const int* in_sizes, int n_in,
                              void* d_out, int out_size) {
    const float* x  = (const float*)d_in[0];
    const int*   ty = (const int*)d_in[1];
    const float* w  = (const float*)d_in[2];
    const float* b  = (const float*)d_in[3];

    int batch = in_sizes[0] / DIMX;
    int chunk = (batch + NBLK - 1) / NBLK;

    k_hist   <<<NBLK, 256>>>(ty, batch, chunk);
    k_scatter<<<NBLK, 256>>>(ty, batch, chunk);
    k_stats  <<<NBLK, 256>>>(x, w, b, batch, chunk);

    int n4 = batch * (DIMX / 4);
    k_apply<<<(n4 + 1023) / 1024, 256>>>((const float4*)x, ty, (float4*)d_out, n4);
}